// round 12
// baseline (speedup 1.0000x reference)
#include <cuda_runtime.h>
#include <math.h>

#define NPIX (1024*1024)
#define NTOT (4*NPIX)
#define EPSF 1e-8f

#define GRID_MAIN 1024
#define BLK 256

// ---------------- scratch state (static device memory; no allocs) -----------
__device__ float g_V[3*NPIX];        // optical density, (3,N)
__device__ float g_W[NPIX*4];        // concentrations Wc, (N,4) row-major (float4 per pixel)
__device__ float g_Hd[12];           // stain matrix (3,4)
__device__ float g_G[16];            // Gram Hd^T Hd (4,4)
__device__ float g_A[12];            // V @ Wc   (3,4) accumulator
__device__ float g_B[10];            // Wc^T Wc upper triangle (j<=r)
__device__ unsigned int g_counter;   // last-block counter
// quantile select state
__device__ unsigned int g_hist[2048];
__device__ unsigned int g_prefix;
__device__ unsigned long long g_krem;
__device__ unsigned int g_vk;
__device__ unsigned int g_cle;
__device__ unsigned int g_mingt;
__device__ float g_scale;

// ---------------- init: V = -log(clip(pic)) ---------------------------------
__global__ void k_V(const float* __restrict__ pic) {
    int stride = gridDim.x * blockDim.x;
    for (int i = blockIdx.x * blockDim.x + threadIdx.x; i < 3*NPIX; i += stride) {
        float p = pic[i];
        p = fminf(fmaxf(p, 0.01f), 0.99f);
        g_V[i] = -logf(p);
    }
}

__global__ void k_copyW(const float4* __restrict__ W0) {
    int stride = gridDim.x * blockDim.x;
    float4* W4 = reinterpret_cast<float4*>(g_W);
    for (int i = blockIdx.x * blockDim.x + threadIdx.x; i < NPIX; i += stride)
        W4[i] = W0[i];
}

__global__ void k_init(const float* __restrict__ H0) {
    int tid = threadIdx.x;
    if (tid < 12) { g_Hd[tid] = H0[tid]; g_A[tid] = 0.f; }
    if (tid < 10) g_B[tid] = 0.f;
    if (tid < 16) {
        int j = tid >> 2, r = tid & 3;
        g_G[tid] = H0[j]*H0[r] + H0[4+j]*H0[4+r] + H0[8+j]*H0[8+r];
    }
    if (tid == 0) {
        g_counter = 0u;
        g_prefix = 0u;
        double pos = 0.99 * (double)(NTOT - 1);
        g_krem = (unsigned long long)((long long)pos);   // 4152359
    }
    for (int i = tid; i < 2048; i += blockDim.x) g_hist[i] = 0u;
}

// ---------------- main NMF iteration kernel ---------------------------------
// Wc_new = Wc * (V^T Hd) / (Wc G + eps)   (elementwise per pixel)
// if REDUCE: accumulate A = V @ Wc_new (3x4), B = Wc_new^T Wc_new (sym 10)
// last block: Hd_new = Hd * A / (Hd B + eps); G = Hd_new^T Hd_new; zero acc.
template<bool REDUCE>
__global__ void __launch_bounds__(BLK) k_main() {
    __shared__ float sHd[12], sG[16];
    int tid = threadIdx.x;
    if (tid < 12) sHd[tid] = g_Hd[tid];
    if (tid < 16) sG[tid]  = g_G[tid];
    __syncthreads();

    float hd[12], G[16];
#pragma unroll
    for (int i = 0; i < 12; i++) hd[i] = sHd[i];
#pragma unroll
    for (int i = 0; i < 16; i++) G[i]  = sG[i];

    float aA[12], aB[10];
    if (REDUCE) {
#pragma unroll
        for (int i = 0; i < 12; i++) aA[i] = 0.f;
#pragma unroll
        for (int i = 0; i < 10; i++) aB[i] = 0.f;
    }

    float4* W4 = reinterpret_cast<float4*>(g_W);
    int stride = gridDim.x * blockDim.x;
    for (int n = blockIdx.x * blockDim.x + tid; n < NPIX; n += stride) {
        float v0 = g_V[n], v1 = g_V[NPIX + n], v2 = g_V[2*NPIX + n];
        float4 w = W4[n];
        float wo[4] = {w.x, w.y, w.z, w.w};
        float wn[4];
#pragma unroll
        for (int r = 0; r < 4; r++) {
            float num = v0*hd[r] + v1*hd[4+r] + v2*hd[8+r];
            float den = wo[0]*G[r] + wo[1]*G[4+r] + wo[2]*G[8+r] + wo[3]*G[12+r] + EPSF;
            wn[r] = wo[r] * num / den;
        }
        W4[n] = make_float4(wn[0], wn[1], wn[2], wn[3]);
        if (REDUCE) {
#pragma unroll
            for (int r = 0; r < 4; r++) {
                aA[r]   += v0 * wn[r];
                aA[4+r] += v1 * wn[r];
                aA[8+r] += v2 * wn[r];
            }
            int t = 0;
#pragma unroll
            for (int j = 0; j < 4; j++)
#pragma unroll
                for (int r = j; r < 4; r++) { aB[t] += wn[j] * wn[r]; t++; }
        }
    }

    if (REDUCE) {
        // warp reduce all 22 partials
#pragma unroll
        for (int off = 16; off > 0; off >>= 1) {
#pragma unroll
            for (int i = 0; i < 12; i++) aA[i] += __shfl_down_sync(0xffffffffu, aA[i], off);
#pragma unroll
            for (int i = 0; i < 10; i++) aB[i] += __shfl_down_sync(0xffffffffu, aB[i], off);
        }
        __shared__ float sAcc[22];
        if (tid < 22) sAcc[tid] = 0.f;
        __syncthreads();
        if ((tid & 31) == 0) {
#pragma unroll
            for (int i = 0; i < 12; i++) atomicAdd(&sAcc[i], aA[i]);
#pragma unroll
            for (int i = 0; i < 10; i++) atomicAdd(&sAcc[12+i], aB[i]);
        }
        __syncthreads();
        if (tid < 12)       atomicAdd(&g_A[tid], sAcc[tid]);
        else if (tid < 22)  atomicAdd(&g_B[tid-12], sAcc[tid]);
        __threadfence();
        __syncthreads();

        __shared__ unsigned int lastFlag;
        if (tid == 0)
            lastFlag = (atomicAdd(&g_counter, 1u) == (unsigned)gridDim.x - 1u) ? 1u : 0u;
        __syncthreads();

        if (lastFlag && tid == 0) {
            float A[12], Bt[10];
#pragma unroll
            for (int i = 0; i < 12; i++) A[i]  = *((volatile float*)&g_A[i]);
#pragma unroll
            for (int i = 0; i < 10; i++) Bt[i] = *((volatile float*)&g_B[i]);
            // expand symmetric B
            float Bf[16];
            {
                int t = 0;
                for (int j = 0; j < 4; j++)
                    for (int r = j; r < 4; r++) { Bf[j*4+r] = Bt[t]; Bf[r*4+j] = Bt[t]; t++; }
            }
            float Hn[12];
            for (int c = 0; c < 3; c++)
                for (int r = 0; r < 4; r++) {
                    float den = hd[c*4+0]*Bf[r] + hd[c*4+1]*Bf[4+r]
                              + hd[c*4+2]*Bf[8+r] + hd[c*4+3]*Bf[12+r] + EPSF;
                    Hn[c*4+r] = hd[c*4+r] * A[c*4+r] / den;
                }
            for (int i = 0; i < 12; i++) { g_Hd[i] = Hn[i]; g_A[i] = 0.f; }
            for (int j = 0; j < 4; j++)
                for (int r = 0; r < 4; r++)
                    g_G[j*4+r] = Hn[j]*Hn[r] + Hn[4+j]*Hn[4+r] + Hn[8+j]*Hn[8+r];
            int t = 0;
            for (int j = 0; j < 4; j++)
                for (int r = j; r < 4; r++) { g_B[t] = 0.f; t++; }
            __threadfence();
            g_counter = 0u;
        }
    }
}

// ---------------- quantile: radix select on float bits ----------------------
__global__ void k_hist(unsigned int prefmask, int shift, int nbins) {
    __shared__ unsigned int sh[2048];
    int tid = threadIdx.x;
    for (int i = tid; i < nbins; i += blockDim.x) sh[i] = 0u;
    __syncthreads();
    unsigned int pref = g_prefix;
    int stride = gridDim.x * blockDim.x;
    for (int i = blockIdx.x * blockDim.x + tid; i < NTOT; i += stride) {
        unsigned int b = __float_as_uint(g_W[i]);
        if ((b & prefmask) == pref)
            atomicAdd(&sh[(b >> shift) & (unsigned)(nbins - 1)], 1u);
    }
    __syncthreads();
    for (int i = tid; i < nbins; i += blockDim.x)
        if (sh[i]) atomicAdd(&g_hist[i], sh[i]);
}

__global__ void k_scan(int shift, int nbins, int final_) {
    __shared__ unsigned int sh[2048];
    __shared__ unsigned int csum[64];
    int tid = threadIdx.x;
    for (int i = tid; i < nbins; i += blockDim.x) sh[i] = g_hist[i];
    __syncthreads();
    int chunk = nbins / 64;
    if (tid < 64) {
        unsigned int s = 0;
        for (int i = 0; i < chunk; i++) s += sh[tid*chunk + i];
        csum[tid] = s;
    }
    __syncthreads();
    if (tid == 0) {
        unsigned long long krem = g_krem;
        unsigned long long cum = 0;
        int cc = 0;
        for (; cc < 63; cc++) { if (cum + csum[cc] > krem) break; cum += csum[cc]; }
        int b = cc * chunk;
        for (; b < nbins - 1; b++) { if (cum + sh[b] > krem) break; cum += sh[b]; }
        g_krem = krem - cum;
        unsigned int pref = g_prefix | ((unsigned int)b << shift);
        g_prefix = pref;
        if (final_) { g_vk = pref; g_cle = 0u; g_mingt = 0xFFFFFFFFu; }
    }
    __syncthreads();
    for (int i = tid; i < nbins; i += blockDim.x) g_hist[i] = 0u;
}

// count elements <= v_k and min element > v_k (for the k+1 order statistic)
__global__ void k_pass4() {
    unsigned int vk = g_vk;
    unsigned int cnt = 0, mn = 0xFFFFFFFFu;
    int tid = threadIdx.x;
    int stride = gridDim.x * blockDim.x;
    for (int i = blockIdx.x * blockDim.x + tid; i < NTOT; i += stride) {
        unsigned int b = __float_as_uint(g_W[i]);
        if (b <= vk) cnt++;
        else mn = min(mn, b);
    }
#pragma unroll
    for (int off = 16; off > 0; off >>= 1) {
        cnt += __shfl_down_sync(0xffffffffu, cnt, off);
        mn  = min(mn, __shfl_down_sync(0xffffffffu, mn, off));
    }
    __shared__ unsigned int scnt; __shared__ unsigned int smn;
    if (tid == 0) { scnt = 0u; smn = 0xFFFFFFFFu; }
    __syncthreads();
    if ((tid & 31) == 0) { atomicAdd(&scnt, cnt); atomicMin(&smn, mn); }
    __syncthreads();
    if (tid == 0) { atomicAdd(&g_cle, scnt); atomicMin(&g_mingt, smn); }
}

__global__ void k_scale(const float* __restrict__ HtRM) {
    if (threadIdx.x == 0 && blockIdx.x == 0) {
        double pos = 0.99 * (double)(NTOT - 1);
        long long k = (long long)pos;
        double frac = pos - (double)k;
        float ak = __uint_as_float(g_vk);
        float ak1 = ((long long)g_cle >= k + 2) ? ak : __uint_as_float(g_mingt);
        double q = (double)ak + frac * ((double)ak1 - (double)ak);
        g_scale = (float)((double)HtRM[0] / q);
    }
}

// ---------------- final recomposition ---------------------------------------
__global__ void k_out(const float* __restrict__ Wt, float* __restrict__ out) {
    __shared__ float sWt[12];
    int tid = threadIdx.x;
    if (tid < 12) sWt[tid] = Wt[tid];
    __syncthreads();
    float s = g_scale;
    const float4* W4 = reinterpret_cast<const float4*>(g_W);
    int stride = gridDim.x * blockDim.x;
    for (int n = blockIdx.x * blockDim.x + tid; n < NPIX; n += stride) {
        float4 w = W4[n];
#pragma unroll
        for (int c = 0; c < 3; c++) {
            float x = (sWt[c*4]*w.x + sWt[c*4+1]*w.y + sWt[c*4+2]*w.z + sWt[c*4+3]*w.w) * s;
            out[c*NPIX + n] = __saturatef(expf(-x));
        }
    }
}

// ---------------- launcher ---------------------------------------------------
extern "C" void kernel_launch(void* const* d_in, const int* in_sizes, int n_in,
                              void* d_out, int out_size) {
    (void)in_sizes; (void)n_in; (void)out_size;
    const float*  pic   = (const float*)d_in[0];
    const float*  Wt    = (const float*)d_in[1];   // W_target (3,4)
    const float*  HtRM  = (const float*)d_in[2];   // scalar
    const float4* W0    = (const float4*)d_in[3];  // (N,4)
    const float*  H0    = (const float*)d_in[4];   // (3,4)
    float* out = (float*)d_out;

    k_V<<<GRID_MAIN, BLK>>>(pic);
    k_copyW<<<GRID_MAIN, BLK>>>(W0);
    k_init<<<1, 256>>>(H0);

    // 100 Wc updates; the reference's 100th Hd update never affects the output,
    // so the last iteration skips reductions entirely.
    for (int it = 0; it < 99; ++it)
        k_main<true><<<GRID_MAIN, BLK>>>();
    k_main<false><<<GRID_MAIN, BLK>>>();

    // exact 0.99-quantile over all 4N concentrations via 3-pass radix select
    k_hist<<<GRID_MAIN, BLK>>>(0x00000000u, 21, 2048);
    k_scan<<<1, 256>>>(21, 2048, 0);
    k_hist<<<GRID_MAIN, BLK>>>(0xFFE00000u, 10, 2048);
    k_scan<<<1, 256>>>(10, 2048, 0);
    k_hist<<<GRID_MAIN, BLK>>>(0xFFFFFC00u, 0, 1024);
    k_scan<<<1, 256>>>(0, 1024, 1);
    k_pass4<<<GRID_MAIN, BLK>>>();
    k_scale<<<1, 32>>>(HtRM);

    k_out<<<GRID_MAIN, BLK>>>(Wt, out);
}

// round 17
// speedup vs baseline: 1.0916x; 1.0916x over previous
#include <cuda_runtime.h>
#include <math.h>

#define NPIX (1024*1024)
#define NTOT (4*NPIX)
#define EPSF 1e-8f

#define GRID_MAIN 1024
#define BLK 256
#define STRIDE (GRID_MAIN*BLK)        // 262144 threads
#define UNROLL 4                      // NPIX / STRIDE == 4 exactly

// ---------------- scratch state (static device memory; no allocs) -----------
__device__ float g_V[4*NPIX];        // optical density packed float4 per pixel (v0,v1,v2,0)
__device__ float g_W[NPIX*4];        // concentrations Wc, (N,4) row-major (float4 per pixel)
__device__ float g_Hd[12];           // stain matrix (3,4)
__device__ float g_G[16];            // Gram Hd^T Hd (4,4)
__device__ float g_A[12];            // V @ Wc   (3,4) accumulator
__device__ float g_B[10];            // Wc^T Wc upper triangle (j<=r)
__device__ unsigned int g_counter;   // last-block counter
// quantile select state
__device__ unsigned int g_hist[2048];
__device__ unsigned int g_prefix;
__device__ unsigned long long g_krem;
__device__ unsigned int g_vk;
__device__ unsigned int g_cle;
__device__ unsigned int g_mingt;
__device__ float g_scale;

// ---------------- init: V4 = (-log(clip(pic_rgb)), 0) -----------------------
__global__ void k_V(const float* __restrict__ pic) {
    float4* V4 = reinterpret_cast<float4*>(g_V);
    int stride = gridDim.x * blockDim.x;
    for (int n = blockIdx.x * blockDim.x + threadIdx.x; n < NPIX; n += stride) {
        float p0 = fminf(fmaxf(pic[n],        0.01f), 0.99f);
        float p1 = fminf(fmaxf(pic[NPIX+n],   0.01f), 0.99f);
        float p2 = fminf(fmaxf(pic[2*NPIX+n], 0.01f), 0.99f);
        V4[n] = make_float4(-logf(p0), -logf(p1), -logf(p2), 0.f);
    }
}

__global__ void k_copyW(const float4* __restrict__ W0) {
    int stride = gridDim.x * blockDim.x;
    float4* W4 = reinterpret_cast<float4*>(g_W);
    for (int i = blockIdx.x * blockDim.x + threadIdx.x; i < NPIX; i += stride)
        W4[i] = W0[i];
}

__global__ void k_init(const float* __restrict__ H0) {
    int tid = threadIdx.x;
    if (tid < 12) { g_Hd[tid] = H0[tid]; g_A[tid] = 0.f; }
    if (tid < 10) g_B[tid] = 0.f;
    if (tid < 16) {
        int j = tid >> 2, r = tid & 3;
        g_G[tid] = H0[j]*H0[r] + H0[4+j]*H0[4+r] + H0[8+j]*H0[8+r];
    }
    if (tid == 0) {
        g_counter = 0u;
        g_prefix = 0u;
        double pos = 0.99 * (double)(NTOT - 1);
        g_krem = (unsigned long long)((long long)pos);   // 4152359
    }
    for (int i = tid; i < 2048; i += blockDim.x) g_hist[i] = 0u;
}

// ---------------- main NMF iteration kernel ---------------------------------
// Wc_new = Wc * (V^T Hd) / (Wc G + eps)   (elementwise per pixel)
// if REDUCE: accumulate A = V @ Wc_new (3x4), B = Wc_new^T Wc_new (sym 10)
// last block: Hd_new = Hd * A / (Hd B + eps); G = Hd_new^T Hd_new; zero acc.
template<bool REDUCE>
__global__ void __launch_bounds__(BLK) k_main() {
    __shared__ float sHd[12], sG[16];
    int tid = threadIdx.x;
    if (tid < 12) sHd[tid] = g_Hd[tid];
    if (tid < 16) sG[tid]  = g_G[tid];
    __syncthreads();

    float hd[12], G[16];
#pragma unroll
    for (int i = 0; i < 12; i++) hd[i] = sHd[i];
#pragma unroll
    for (int i = 0; i < 16; i++) G[i]  = sG[i];

    const float4* V4 = reinterpret_cast<const float4*>(g_V);
    float4* W4 = reinterpret_cast<float4*>(g_W);
    int n0 = blockIdx.x * BLK + tid;

    // front-batch ALL loads for maximum MLP (L2-latency hiding)
    float4 v[UNROLL], w[UNROLL];
#pragma unroll
    for (int k = 0; k < UNROLL; k++) {
        v[k] = V4[n0 + k*STRIDE];
        w[k] = W4[n0 + k*STRIDE];
    }

    float aA[12], aB[10];
    if (REDUCE) {
#pragma unroll
        for (int i = 0; i < 12; i++) aA[i] = 0.f;
#pragma unroll
        for (int i = 0; i < 10; i++) aB[i] = 0.f;
    }

#pragma unroll
    for (int k = 0; k < UNROLL; k++) {
        float wo[4] = {w[k].x, w[k].y, w[k].z, w[k].w};
        float wn[4];
#pragma unroll
        for (int r = 0; r < 4; r++) {
            float num = fmaf(v[k].z, hd[8+r], fmaf(v[k].y, hd[4+r], v[k].x*hd[r]));
            float den = fmaf(wo[0], G[r],
                        fmaf(wo[1], G[4+r],
                        fmaf(wo[2], G[8+r],
                        fmaf(wo[3], G[12+r], EPSF))));
            wn[r] = wo[r] * __fdividef(num, den);
        }
        W4[n0 + k*STRIDE] = make_float4(wn[0], wn[1], wn[2], wn[3]);
        if (REDUCE) {
#pragma unroll
            for (int r = 0; r < 4; r++) {
                aA[r]   = fmaf(v[k].x, wn[r], aA[r]);
                aA[4+r] = fmaf(v[k].y, wn[r], aA[4+r]);
                aA[8+r] = fmaf(v[k].z, wn[r], aA[8+r]);
            }
            int t = 0;
#pragma unroll
            for (int j = 0; j < 4; j++)
#pragma unroll
                for (int r = j; r < 4; r++) { aB[t] = fmaf(wn[j], wn[r], aB[t]); t++; }
        }
    }

    if (REDUCE) {
        // warp reduce all 22 partials
#pragma unroll
        for (int off = 16; off > 0; off >>= 1) {
#pragma unroll
            for (int i = 0; i < 12; i++) aA[i] += __shfl_down_sync(0xffffffffu, aA[i], off);
#pragma unroll
            for (int i = 0; i < 10; i++) aB[i] += __shfl_down_sync(0xffffffffu, aB[i], off);
        }
        __shared__ float sAcc[22];
        if (tid < 22) sAcc[tid] = 0.f;
        __syncthreads();
        if ((tid & 31) == 0) {
#pragma unroll
            for (int i = 0; i < 12; i++) atomicAdd(&sAcc[i], aA[i]);
#pragma unroll
            for (int i = 0; i < 10; i++) atomicAdd(&sAcc[12+i], aB[i]);
        }
        __syncthreads();
        if (tid < 12)       atomicAdd(&g_A[tid], sAcc[tid]);
        else if (tid < 22)  atomicAdd(&g_B[tid-12], sAcc[tid]);
        __threadfence();
        __syncthreads();

        __shared__ unsigned int lastFlag;
        if (tid == 0)
            lastFlag = (atomicAdd(&g_counter, 1u) == (unsigned)gridDim.x - 1u) ? 1u : 0u;
        __syncthreads();

        if (lastFlag && tid == 0) {
            float A[12], Bt[10];
#pragma unroll
            for (int i = 0; i < 12; i++) A[i]  = *((volatile float*)&g_A[i]);
#pragma unroll
            for (int i = 0; i < 10; i++) Bt[i] = *((volatile float*)&g_B[i]);
            // expand symmetric B
            float Bf[16];
            {
                int t = 0;
                for (int j = 0; j < 4; j++)
                    for (int r = j; r < 4; r++) { Bf[j*4+r] = Bt[t]; Bf[r*4+j] = Bt[t]; t++; }
            }
            float Hn[12];
            for (int c = 0; c < 3; c++)
                for (int r = 0; r < 4; r++) {
                    float den = hd[c*4+0]*Bf[r] + hd[c*4+1]*Bf[4+r]
                              + hd[c*4+2]*Bf[8+r] + hd[c*4+3]*Bf[12+r] + EPSF;
                    Hn[c*4+r] = hd[c*4+r] * A[c*4+r] / den;
                }
            for (int i = 0; i < 12; i++) { g_Hd[i] = Hn[i]; g_A[i] = 0.f; }
            for (int j = 0; j < 4; j++)
                for (int r = 0; r < 4; r++)
                    g_G[j*4+r] = Hn[j]*Hn[r] + Hn[4+j]*Hn[4+r] + Hn[8+j]*Hn[8+r];
            int t = 0;
            for (int j = 0; j < 4; j++)
                for (int r = j; r < 4; r++) { g_B[t] = 0.f; t++; }
            __threadfence();
            g_counter = 0u;
        }
    }
}

// ---------------- quantile: radix select on float bits ----------------------
__global__ void k_hist(unsigned int prefmask, int shift, int nbins) {
    __shared__ unsigned int sh[2048];
    int tid = threadIdx.x;
    for (int i = tid; i < nbins; i += blockDim.x) sh[i] = 0u;
    __syncthreads();
    unsigned int pref = g_prefix;
    int stride = gridDim.x * blockDim.x;
    for (int i = blockIdx.x * blockDim.x + tid; i < NTOT; i += stride) {
        unsigned int b = __float_as_uint(g_W[i]);
        if ((b & prefmask) == pref)
            atomicAdd(&sh[(b >> shift) & (unsigned)(nbins - 1)], 1u);
    }
    __syncthreads();
    for (int i = tid; i < nbins; i += blockDim.x)
        if (sh[i]) atomicAdd(&g_hist[i], sh[i]);
}

__global__ void k_scan(int shift, int nbins, int final_) {
    __shared__ unsigned int sh[2048];
    __shared__ unsigned int csum[64];
    int tid = threadIdx.x;
    for (int i = tid; i < nbins; i += blockDim.x) sh[i] = g_hist[i];
    __syncthreads();
    int chunk = nbins / 64;
    if (tid < 64) {
        unsigned int s = 0;
        for (int i = 0; i < chunk; i++) s += sh[tid*chunk + i];
        csum[tid] = s;
    }
    __syncthreads();
    if (tid == 0) {
        unsigned long long krem = g_krem;
        unsigned long long cum = 0;
        int cc = 0;
        for (; cc < 63; cc++) { if (cum + csum[cc] > krem) break; cum += csum[cc]; }
        int b = cc * chunk;
        for (; b < nbins - 1; b++) { if (cum + sh[b] > krem) break; cum += sh[b]; }
        g_krem = krem - cum;
        unsigned int pref = g_prefix | ((unsigned int)b << shift);
        g_prefix = pref;
        if (final_) { g_vk = pref; g_cle = 0u; g_mingt = 0xFFFFFFFFu; }
    }
    __syncthreads();
    for (int i = tid; i < nbins; i += blockDim.x) g_hist[i] = 0u;
}

// count elements <= v_k and min element > v_k (for the k+1 order statistic)
__global__ void k_pass4() {
    unsigned int vk = g_vk;
    unsigned int cnt = 0, mn = 0xFFFFFFFFu;
    int tid = threadIdx.x;
    int stride = gridDim.x * blockDim.x;
    for (int i = blockIdx.x * blockDim.x + tid; i < NTOT; i += stride) {
        unsigned int b = __float_as_uint(g_W[i]);
        if (b <= vk) cnt++;
        else mn = min(mn, b);
    }
#pragma unroll
    for (int off = 16; off > 0; off >>= 1) {
        cnt += __shfl_down_sync(0xffffffffu, cnt, off);
        mn  = min(mn, __shfl_down_sync(0xffffffffu, mn, off));
    }
    __shared__ unsigned int scnt; __shared__ unsigned int smn;
    if (tid == 0) { scnt = 0u; smn = 0xFFFFFFFFu; }
    __syncthreads();
    if ((tid & 31) == 0) { atomicAdd(&scnt, cnt); atomicMin(&smn, mn); }
    __syncthreads();
    if (tid == 0) { atomicAdd(&g_cle, scnt); atomicMin(&g_mingt, smn); }
}

__global__ void k_scale(const float* __restrict__ HtRM) {
    if (threadIdx.x == 0 && blockIdx.x == 0) {
        double pos = 0.99 * (double)(NTOT - 1);
        long long k = (long long)pos;
        double frac = pos - (double)k;
        float ak = __uint_as_float(g_vk);
        float ak1 = ((long long)g_cle >= k + 2) ? ak : __uint_as_float(g_mingt);
        double q = (double)ak + frac * ((double)ak1 - (double)ak);
        g_scale = (float)((double)HtRM[0] / q);
    }
}

// ---------------- final recomposition ---------------------------------------
__global__ void k_out(const float* __restrict__ Wt, float* __restrict__ out) {
    __shared__ float sWt[12];
    int tid = threadIdx.x;
    if (tid < 12) sWt[tid] = Wt[tid];
    __syncthreads();
    float s = g_scale;
    const float4* W4 = reinterpret_cast<const float4*>(g_W);
    int stride = gridDim.x * blockDim.x;
    for (int n = blockIdx.x * blockDim.x + tid; n < NPIX; n += stride) {
        float4 w = W4[n];
#pragma unroll
        for (int c = 0; c < 3; c++) {
            float x = (sWt[c*4]*w.x + sWt[c*4+1]*w.y + sWt[c*4+2]*w.z + sWt[c*4+3]*w.w) * s;
            out[c*NPIX + n] = __saturatef(expf(-x));
        }
    }
}

// ---------------- launcher ---------------------------------------------------
extern "C" void kernel_launch(void* const* d_in, const int* in_sizes, int n_in,
                              void* d_out, int out_size) {
    (void)in_sizes; (void)n_in; (void)out_size;
    const float*  pic   = (const float*)d_in[0];
    const float*  Wt    = (const float*)d_in[1];   // W_target (3,4)
    const float*  HtRM  = (const float*)d_in[2];   // scalar
    const float4* W0    = (const float4*)d_in[3];  // (N,4)
    const float*  H0    = (const float*)d_in[4];   // (3,4)
    float* out = (float*)d_out;

    k_V<<<GRID_MAIN, BLK>>>(pic);
    k_copyW<<<GRID_MAIN, BLK>>>(W0);
    k_init<<<1, 256>>>(H0);

    // 100 Wc updates; the reference's 100th Hd update never affects the output,
    // so the last iteration skips reductions entirely.
    for (int it = 0; it < 99; ++it)
        k_main<true><<<GRID_MAIN, BLK>>>();
    k_main<false><<<GRID_MAIN, BLK>>>();

    // exact 0.99-quantile over all 4N concentrations via 3-pass radix select
    k_hist<<<GRID_MAIN, BLK>>>(0x00000000u, 21, 2048);
    k_scan<<<1, 256>>>(21, 2048, 0);
    k_hist<<<GRID_MAIN, BLK>>>(0xFFE00000u, 10, 2048);
    k_scan<<<1, 256>>>(10, 2048, 0);
    k_hist<<<GRID_MAIN, BLK>>>(0xFFFFFC00u, 0, 1024);
    k_scan<<<1, 256>>>(0, 1024, 1);
    k_pass4<<<GRID_MAIN, BLK>>>();
    k_scale<<<1, 32>>>(HtRM);

    k_out<<<GRID_MAIN, BLK>>>(Wt, out);
}